// round 3
// baseline (speedup 1.0000x reference)
#include <cuda_runtime.h>
#include <math.h>

#define H 1024
#define NC 3
#define B 128
#define T 128
#define G3 (3*H)   // 3072

// ---------------- scratch (device globals; no allocation allowed) ----------------
__device__ float g_gx[(size_t)B*T*G3];   // 192 MB: gates_x [b*T+t, 3H]; reused as Wy [t*B+b, H]
__device__ float g_op[(size_t)T*B*H];    // 64 MB: premise GRU outputs, layout [t][b][h]
__device__ float g_hA[B*H];
__device__ float g_hB[B*H];
__device__ float g_gh[B*G3];
__device__ float g_wh[B*H];
__device__ float g_sc[B*T];
__device__ float g_al[B*T];
__device__ float g_r[B*H];
__device__ float g_tmp[B*H];

// ---------------- big GEMM: C[M,N] = A[M,K] @ B (+bias). BM=BN=128, BK=8, 256 thr, 8x8 microtile
// TRANSB: B is [N,K] row-major (C = A @ B^T). else B is [K,N] row-major.
template<bool TRANSB, bool ACCUM, bool BIAS>
__global__ void gemm128(const float* __restrict__ A, const float* __restrict__ Bm,
                        const float* __restrict__ bias, float* __restrict__ Cm,
                        int M, int N, int K)
{
    __shared__ float As[8][128];
    __shared__ float Bs[8][128];
    int tid = threadIdx.x;
    int bm = blockIdx.y * 128;
    int bn = blockIdx.x * 128;
    int trow = (tid / 16) * 8;
    int tcol = (tid % 16) * 8;
    float acc[8][8] = {};

    int a_row = tid >> 1;
    int a_k4  = (tid & 1) * 4;

    for (int k0 = 0; k0 < K; k0 += 8) {
        float4 av = *(const float4*)&A[(size_t)(bm + a_row)*K + k0 + a_k4];
        As[a_k4+0][a_row] = av.x;
        As[a_k4+1][a_row] = av.y;
        As[a_k4+2][a_row] = av.z;
        As[a_k4+3][a_row] = av.w;
        if (TRANSB) {
            int n  = tid >> 1;
            int k4 = (tid & 1) * 4;
            float4 bv = *(const float4*)&Bm[(size_t)(bn + n)*K + k0 + k4];
            Bs[k4+0][n] = bv.x; Bs[k4+1][n] = bv.y;
            Bs[k4+2][n] = bv.z; Bs[k4+3][n] = bv.w;
        } else {
            int kr = tid >> 5;
            int n4 = (tid & 31) * 4;
            float4 bv = *(const float4*)&Bm[(size_t)(k0 + kr)*N + bn + n4];
            *(float4*)&Bs[kr][n4] = bv;
        }
        __syncthreads();
        #pragma unroll
        for (int k = 0; k < 8; k++) {
            float a_frag[8], b_frag[8];
            #pragma unroll
            for (int i = 0; i < 8; i++) a_frag[i] = As[k][trow + i];
            #pragma unroll
            for (int j = 0; j < 8; j++) b_frag[j] = Bs[k][tcol + j];
            #pragma unroll
            for (int i = 0; i < 8; i++)
                #pragma unroll
                for (int j = 0; j < 8; j++)
                    acc[i][j] += a_frag[i] * b_frag[j];
        }
        __syncthreads();
    }

    #pragma unroll
    for (int i = 0; i < 8; i++) {
        size_t row = (size_t)(bm + trow + i);
        #pragma unroll
        for (int j = 0; j < 8; j += 4) {
            int col = bn + tcol + j;
            float4 v = { acc[i][j], acc[i][j+1], acc[i][j+2], acc[i][j+3] };
            if (BIAS) { v.x += bias[col]; v.y += bias[col+1]; v.z += bias[col+2]; v.w += bias[col+3]; }
            if (ACCUM) {
                float4 o = *(const float4*)&Cm[row*N + col];
                v.x += o.x; v.y += o.y; v.z += o.z; v.w += o.w;
            }
            *(float4*)&Cm[row*N + col] = v;
        }
    }
}

// ---------------- small-M GEMM: M must be 128. BM=128, BN=32, BK=16, 128 thr, 8x4 microtile
template<bool TRANSB, bool ACCUM, bool BIAS>
__global__ void gemm_smallM(const float* __restrict__ A, const float* __restrict__ Bm,
                            const float* __restrict__ bias, float* __restrict__ Cm,
                            int N, int K)
{
    __shared__ float As[16][128];
    __shared__ float Bs[16][32];
    int tid = threadIdx.x;
    int bn = blockIdx.x * 32;
    int ty = tid >> 3;          // 0..15
    int tx = tid & 7;           // 0..7
    int trow = ty * 8, tcol = tx * 4;
    float acc[8][4] = {};

    for (int k0 = 0; k0 < K; k0 += 16) {
        #pragma unroll
        for (int l = 0; l < 4; l++) {
            int idx = tid + l * 128;       // 0..511 float4 slots
            int row = idx >> 2;
            int k4  = (idx & 3) * 4;
            float4 av = *(const float4*)&A[(size_t)row*K + k0 + k4];
            As[k4+0][row] = av.x; As[k4+1][row] = av.y;
            As[k4+2][row] = av.z; As[k4+3][row] = av.w;
        }
        if (TRANSB) {
            int n  = tid >> 2;            // 0..31
            int k4 = (tid & 3) * 4;
            float4 bv = *(const float4*)&Bm[(size_t)(bn + n)*K + k0 + k4];
            Bs[k4+0][n] = bv.x; Bs[k4+1][n] = bv.y;
            Bs[k4+2][n] = bv.z; Bs[k4+3][n] = bv.w;
        } else {
            int kr = tid >> 3;            // 0..15
            int n4 = (tid & 7) * 4;
            float4 bv = *(const float4*)&Bm[(size_t)(k0 + kr)*N + bn + n4];
            *(float4*)&Bs[kr][n4] = bv;
        }
        __syncthreads();
        #pragma unroll
        for (int k = 0; k < 16; k++) {
            float b0 = Bs[k][tcol], b1 = Bs[k][tcol+1], b2 = Bs[k][tcol+2], b3 = Bs[k][tcol+3];
            #pragma unroll
            for (int i = 0; i < 8; i++) {
                float a = As[k][trow + i];
                acc[i][0] += a*b0; acc[i][1] += a*b1; acc[i][2] += a*b2; acc[i][3] += a*b3;
            }
        }
        __syncthreads();
    }

    #pragma unroll
    for (int i = 0; i < 8; i++) {
        size_t row = (size_t)(trow + i);
        int col = bn + tcol;
        float4 v = { acc[i][0], acc[i][1], acc[i][2], acc[i][3] };
        if (BIAS) { v.x += bias[col]; v.y += bias[col+1]; v.z += bias[col+2]; v.w += bias[col+3]; }
        if (ACCUM) {
            float4 o = *(const float4*)&Cm[row*N + col];
            v.x += o.x; v.y += o.y; v.z += o.z; v.w += o.w;
        }
        *(float4*)&Cm[row*N + col] = v;
    }
}

// ---------------- GRU gate fusion: h_new from gx[t], gh, h_prev ----------------
__global__ void gru_gate(const float* __restrict__ gx,   // [B*T, 3H]
                         const float* __restrict__ gh,   // [B, 3H]
                         const float* __restrict__ hprev,
                         float* __restrict__ hnext,
                         float* __restrict__ o_t,        // o_p slot [B,H] or nullptr
                         int t)
{
    int idx = blockIdx.x * blockDim.x + threadIdx.x;   // 0..B*H-1
    int b = idx >> 10;
    int j = idx & 1023;
    const float* gxr = gx + (size_t)(b*T + t) * G3;
    const float* ghr = gh + (size_t)b * G3;
    float xr = gxr[j], xz = gxr[j + H], xn = gxr[j + 2*H];
    float hr = ghr[j], hz = ghr[j + H], hn = ghr[j + 2*H];
    float r = 1.f / (1.f + expf(-(xr + hr)));
    float z = 1.f / (1.f + expf(-(xz + hz)));
    float n = tanhf(xn + r * hn);
    float hnew = (1.f - z) * n + z * hprev[idx];
    hnext[idx] = hnew;
    if (o_t) o_t[(size_t)b*H + j] = hnew;
}

// ---------------- attention scores: sc[b,t] = sum_h tanh(wy[p,h]+wh[b,h])*wa[h], p=t*B+b
__global__ void scores_kernel(const float* __restrict__ wy, const float* __restrict__ wh,
                              const float* __restrict__ wa, float* __restrict__ sc)
{
    int warp = threadIdx.x >> 5, lane = threadIdx.x & 31;
    int p = blockIdx.x * 4 + warp;    // p = t*B + b
    int t = p >> 7, b = p & 127;
    const float* wyr = wy + (size_t)p * H;
    const float* whr = wh + (size_t)b * H;
    float acc = 0.f;
    for (int h = lane; h < H; h += 32)
        acc += tanhf(wyr[h] + whr[h]) * wa[h];
    #pragma unroll
    for (int o = 16; o > 0; o >>= 1) acc += __shfl_xor_sync(0xffffffff, acc, o);
    if (lane == 0) sc[b*T + t] = acc;
}

__global__ void softmax_kernel(const float* __restrict__ sc, float* __restrict__ al)
{
    __shared__ float s[128];
    int b = blockIdx.x, t = threadIdx.x;
    float v = sc[b*T + t];
    s[t] = v; __syncthreads();
    for (int o = 64; o > 0; o >>= 1) { if (t < o) s[t] = fmaxf(s[t], s[t + o]); __syncthreads(); }
    float mx = s[0]; __syncthreads();
    float e = expf(v - mx);
    s[t] = e; __syncthreads();
    for (int o = 64; o > 0; o >>= 1) { if (t < o) s[t] += s[t + o]; __syncthreads(); }
    al[b*T + t] = e / s[0];
}

// r[b,h] = sum_t alpha[b,t] * o_p[t,b,h]
__global__ void rweight_kernel(const float* __restrict__ al, const float* __restrict__ op,
                               float* __restrict__ r)
{
    int idx = blockIdx.x * blockDim.x + threadIdx.x;
    int b = idx >> 10, j = idx & 1023;
    float acc = 0.f;
    #pragma unroll 4
    for (int t = 0; t < T; t++)
        acc += al[b*T + t] * op[(size_t)t*B*H + (size_t)b*H + j];
    r[idx] = acc;
}

// logits + log_softmax: tmp holds pre-tanh h_star
__global__ void out_kernel(const float* __restrict__ tmp, const float* __restrict__ ow,
                           const float* __restrict__ ob, float* __restrict__ out)
{
    __shared__ float s0[128], s1[128], s2[128];
    int b = blockIdx.x, tid = threadIdx.x;
    float p0 = 0.f, p1 = 0.f, p2 = 0.f;
    for (int h = tid; h < H; h += 128) {
        float hs = tanhf(tmp[(size_t)b*H + h]);
        p0 += hs * ow[0*H + h];
        p1 += hs * ow[1*H + h];
        p2 += hs * ow[2*H + h];
    }
    s0[tid] = p0; s1[tid] = p1; s2[tid] = p2; __syncthreads();
    for (int o = 64; o > 0; o >>= 1) {
        if (tid < o) { s0[tid] += s0[tid+o]; s1[tid] += s1[tid+o]; s2[tid] += s2[tid+o]; }
        __syncthreads();
    }
    if (tid == 0) {
        float l0 = tanhf(s0[0] + ob[0]);
        float l1 = tanhf(s1[0] + ob[1]);
        float l2 = tanhf(s2[0] + ob[2]);
        float mx = fmaxf(l0, fmaxf(l1, l2));
        float e0 = expf(l0 - mx), e1 = expf(l1 - mx), e2 = expf(l2 - mx);
        float lse = mx + logf(e0 + e1 + e2);
        out[b*3 + 0] = l0 - lse;
        out[b*3 + 1] = l1 - lse;
        out[b*3 + 2] = l2 - lse;
    }
}

// ---------------- launch ----------------
extern "C" void kernel_launch(void* const* d_in, const int* in_sizes, int n_in,
                              void* d_out, int out_size)
{
    const float* premise    = (const float*)d_in[0];
    const float* hypothesis = (const float*)d_in[1];
    const float* p_Wih = (const float*)d_in[2];
    const float* p_Whh = (const float*)d_in[3];
    const float* p_bih = (const float*)d_in[4];
    const float* p_bhh = (const float*)d_in[5];
    const float* h_Wih = (const float*)d_in[6];
    const float* h_Whh = (const float*)d_in[7];
    const float* h_bih = (const float*)d_in[8];
    const float* h_bhh = (const float*)d_in[9];
    const float* W_y     = (const float*)d_in[10];
    const float* W_h     = (const float*)d_in[11];
    const float* W_alpha = (const float*)d_in[12];
    const float* W_x     = (const float*)d_in[13];
    const float* W_p     = (const float*)d_in[14];
    const float* out_w   = (const float*)d_in[15];
    const float* out_b   = (const float*)d_in[16];
    float* out = (float*)d_out;

    float *gx, *op, *hA, *hB, *gh, *wh, *sc, *al, *rr, *tmp;
    cudaGetSymbolAddress((void**)&gx,  g_gx);
    cudaGetSymbolAddress((void**)&op,  g_op);
    cudaGetSymbolAddress((void**)&hA,  g_hA);
    cudaGetSymbolAddress((void**)&hB,  g_hB);
    cudaGetSymbolAddress((void**)&gh,  g_gh);
    cudaGetSymbolAddress((void**)&wh,  g_wh);
    cudaGetSymbolAddress((void**)&sc,  g_sc);
    cudaGetSymbolAddress((void**)&al,  g_al);
    cudaGetSymbolAddress((void**)&rr,  g_r);
    cudaGetSymbolAddress((void**)&tmp, g_tmp);

    cudaMemsetAsync(hA, 0, (size_t)B*H*sizeof(float));

    // gates_x premise: gx[b*T+t, 3H] = premise @ p_Wih^T + p_bih
    gemm128<true,false,true><<<dim3(G3/128, (B*T)/128), 256>>>(premise, p_Wih, p_bih, gx, B*T, G3, H);

    float* hc = hA; float* hn = hB;
    for (int t = 0; t < T; t++) {
        gemm_smallM<true,false,true><<<G3/32, 128>>>(hc, p_Whh, p_bhh, gh, G3, H);
        gru_gate<<<(B*H)/256, 256>>>(gx, gh, hc, hn, op + (size_t)t*B*H, t);
        float* tswap = hc; hc = hn; hn = tswap;
    }

    // gates_x hypothesis (reuse gx buffer)
    gemm128<true,false,true><<<dim3(G3/128, (B*T)/128), 256>>>(hypothesis, h_Wih, h_bih, gx, B*T, G3, H);

    for (int t = 0; t < T; t++) {
        gemm_smallM<true,false,true><<<G3/32, 128>>>(hc, h_Whh, h_bhh, gh, G3, H);
        gru_gate<<<(B*H)/256, 256>>>(gx, gh, hc, hn, nullptr, t);
        float* tswap = hc; hc = hn; hn = tswap;
    }
    // hc == h_final == o_h[-1]

    // Wy[t*B+b, H] = o_p @ W_y  (reuse gx buffer as Wy)
    float* wy = gx;
    gemm128<false,false,false><<<dim3(H/128, (T*B)/128), 256>>>(op, W_y, nullptr, wy, T*B, H, H);
    // Wh = h_final @ W_h
    gemm_smallM<false,false,false><<<H/32, 128>>>(hc, W_h, nullptr, wh, H, H);

    scores_kernel<<<(T*B)/4, 128>>>(wy, wh, W_alpha, sc);
    softmax_kernel<<<B, 128>>>(sc, al);
    rweight_kernel<<<(B*H)/256, 256>>>(al, op, rr);

    // h_star pre-activation: tmp = r @ W_p + h_final @ W_x
    gemm_smallM<false,false,false><<<H/32, 128>>>(rr, W_p, nullptr, tmp, H, H);
    gemm_smallM<false,true ,false><<<H/32, 128>>>(hc, W_x, nullptr, tmp, H, H);

    out_kernel<<<B, 128>>>(tmp, out_w, out_b, out);
}

// round 9
// speedup vs baseline: 2.4444x; 2.4444x over previous
#include <cuda_runtime.h>
#include <cuda_bf16.h>
#include <math.h>
#include <stdint.h>

#define H 1024
#define B 128
#define T 128
#define G3 3072
#define KDIM 1024
#define NCHUNK 16

__device__ __forceinline__ uint32_t smem_u32(const void* p) {
    uint32_t a;
    asm("{ .reg .u64 t; cvta.to.shared.u64 t, %1; cvt.u32.u64 %0, t; }" : "=r"(a) : "l"(p));
    return a;
}
__device__ __forceinline__ void cp16(uint32_t s, const void* g) {
    asm volatile("cp.async.cg.shared.global [%0], [%1], 16;" :: "r"(s), "l"(g));
}
#define CP_COMMIT() asm volatile("cp.async.commit_group;" ::: "memory")
#define CP_WAIT(n) asm volatile("cp.async.wait_group %0;" :: "n"(n) : "memory")
#define LDSM4(r, addr) asm volatile("ldmatrix.sync.aligned.m8n8.x4.shared.b16 {%0,%1,%2,%3}, [%4];" \
    : "=r"((r)[0]),"=r"((r)[1]),"=r"((r)[2]),"=r"((r)[3]) : "r"(addr))
#define MMA(cc, a, b0, b1) asm volatile( \
    "mma.sync.aligned.m16n8k16.row.col.f32.bf16.bf16.f32 {%0,%1,%2,%3},{%4,%5,%6,%7},{%8,%9},{%0,%1,%2,%3};" \
    : "+f"((cc)[0]),"+f"((cc)[1]),"+f"((cc)[2]),"+f"((cc)[3]) \
    : "r"((a)[0]),"r"((a)[1]),"r"((a)[2]),"r"((a)[3]), "r"(b0),"r"(b1))

#define PITCH 144           // bytes per smem row (72 bf16) — 16B aligned, conflict-friendly
#define ABYTES (128*PITCH)  // 18432

#define DEVG __device__ __align__(256)
DEVG float g_gx[(size_t)B*T*G3];
DEVG float g_op[(size_t)B*T*H];
DEVG __nv_bfloat16 g_oph[(size_t)B*T*H];
DEVG __nv_bfloat16 g_opl[(size_t)B*T*H];
DEVG __nv_bfloat16 g_xh[(size_t)B*T*H];
DEVG __nv_bfloat16 g_xl[(size_t)B*T*H];
DEVG __nv_bfloat16 g_wih_h[(size_t)G3*H];
DEVG __nv_bfloat16 g_wih_l[(size_t)G3*H];
DEVG __nv_bfloat16 g_wp_h[(size_t)G3*H];
DEVG __nv_bfloat16 g_wp_l[(size_t)G3*H];
DEVG __nv_bfloat16 g_wyt_h[(size_t)H*H];
DEVG __nv_bfloat16 g_wyt_l[(size_t)H*H];
DEVG float g_h[B*H];
DEVG __nv_bfloat16 g_hhA[B*H], g_hlA[B*H], g_hhB[B*H], g_hlB[B*H];
DEVG float g_wh[B*H];
DEVG float g_sc[B*T];
DEVG float g_al[B*T];
DEVG float g_r[B*H];
DEVG float g_tmp[B*H];

// -------- prep: fp32 -> bf16 hi/lo split --------
__global__ void split4(const float4* __restrict__ x, __nv_bfloat162* __restrict__ hi, __nv_bfloat162* __restrict__ lo)
{
    size_t i = (size_t)blockIdx.x * blockDim.x + threadIdx.x;
    float4 v = x[i];
    __nv_bfloat16 h0 = __float2bfloat16(v.x), h1 = __float2bfloat16(v.y);
    __nv_bfloat16 h2 = __float2bfloat16(v.z), h3 = __float2bfloat16(v.w);
    __nv_bfloat162 a, b;
    a.x = h0; a.y = h1; b.x = h2; b.y = h3;
    hi[2*i] = a; hi[2*i+1] = b;
    a.x = __float2bfloat16(v.x - __bfloat162float(h0));
    a.y = __float2bfloat16(v.y - __bfloat162float(h1));
    b.x = __float2bfloat16(v.z - __bfloat162float(h2));
    b.y = __float2bfloat16(v.w - __bfloat162float(h3));
    lo[2*i] = a; lo[2*i+1] = b;
}
// permuted W_hh: out row c=3j+g <- in row g*H+j, split
__global__ void perm_split(const float* __restrict__ W, __nv_bfloat16* __restrict__ ph, __nv_bfloat16* __restrict__ pl)
{
    size_t i = (size_t)blockIdx.x * blockDim.x + threadIdx.x;
    int c = (int)(i >> 8), k4 = (int)(i & 255) * 4;
    int j = c / 3, g = c - 3*j;
    float4 v = *(const float4*)&W[((size_t)(g*H + j))*H + k4];
    size_t o = (size_t)c*H + k4;
    __nv_bfloat16 h0 = __float2bfloat16(v.x), h1 = __float2bfloat16(v.y);
    __nv_bfloat16 h2 = __float2bfloat16(v.z), h3 = __float2bfloat16(v.w);
    ph[o] = h0; ph[o+1] = h1; ph[o+2] = h2; ph[o+3] = h3;
    pl[o]   = __float2bfloat16(v.x - __bfloat162float(h0));
    pl[o+1] = __float2bfloat16(v.y - __bfloat162float(h1));
    pl[o+2] = __float2bfloat16(v.z - __bfloat162float(h2));
    pl[o+3] = __float2bfloat16(v.w - __bfloat162float(h3));
}
// transpose+split W_y: out[n][k] = W_y[k][n]
__global__ void trans_split(const float* __restrict__ Wy, __nv_bfloat16* __restrict__ th, __nv_bfloat16* __restrict__ tl)
{
    int i = blockIdx.x * blockDim.x + threadIdx.x;
    int n = i >> 10, k = i & 1023;
    float v = Wy[(size_t)k*H + n];
    __nv_bfloat16 hh = __float2bfloat16(v);
    th[(size_t)n*H + k] = hh;
    tl[(size_t)n*H + k] = __float2bfloat16(v - __bfloat162float(hh));
}

// -------- shared bf16x3 K-loop core: 8 warps, each 16 rows x NT cols --------
template<int NT>
__device__ __forceinline__ void mma_loop(uint32_t sb,
    const __nv_bfloat16* __restrict__ Ah, const __nv_bfloat16* __restrict__ Al,
    const __nv_bfloat16* __restrict__ Bh, const __nv_bfloat16* __restrict__ Bl,
    float acc[][4])
{
    const int tid = threadIdx.x, lane = tid & 31, wid = tid >> 5;
    const int m0 = wid * 16;
    const uint32_t BOFF = 2 * ABYTES;
    const uint32_t BBYTES = NT * PITCH;
    const uint32_t BUFB = BOFF + 2 * BBYTES;
    const int lr = lane & 7;
    const uint32_t arow = (uint32_t)(m0 + lr + ((lane >> 3) & 1) * 8);
    const uint32_t acol8 = (uint32_t)((lane >> 4) * 8);
    const uint32_t brow_off = (uint32_t)(lr + (lane >> 4) * 8);
    const uint32_t bcol8 = (uint32_t)(((lane >> 3) & 1) * 8);

    auto load_chunk = [&](int c) {
        uint32_t s0 = sb + (uint32_t)(c & 1) * BUFB;
        int k0 = c * 64;
        #pragma unroll
        for (int i = tid; i < 2048; i += 256) {
            int hl = i >> 10, r = (i >> 3) & 127, s = i & 7;
            cp16(s0 + (uint32_t)(hl*ABYTES + r*PITCH + s*16),
                 (hl ? Al : Ah) + (size_t)r*KDIM + k0 + s*8);
        }
        #pragma unroll
        for (int i = tid; i < NT*16; i += 256) {
            int hl = (i >= NT*8) ? 1 : 0;
            int r = (i >> 3) - hl*NT, s = i & 7;
            cp16(s0 + BOFF + (uint32_t)hl*BBYTES + (uint32_t)(r*PITCH + s*16),
                 (hl ? Bl : Bh) + (size_t)r*KDIM + k0 + s*8);
        }
        CP_COMMIT();
    };

    load_chunk(0);
    for (int c = 0; c < NCHUNK; c++) {
        if (c < NCHUNK - 1) { load_chunk(c + 1); CP_WAIT(1); }
        else CP_WAIT(0);
        __syncthreads();
        uint32_t s0 = sb + (uint32_t)(c & 1) * BUFB;
        #pragma unroll
        for (int ks = 0; ks < 4; ks++) {
            uint32_t aaddr = s0 + arow*PITCH + (ks*16 + acol8)*2;
            uint32_t ah[4], al[4];
            LDSM4(ah, aaddr);
            LDSM4(al, aaddr + ABYTES);
            #pragma unroll
            for (int tt = 0; tt < NT/16; tt++) {
                uint32_t baddr = s0 + BOFF + (tt*16 + brow_off)*PITCH + (ks*16 + bcol8)*2;
                uint32_t bh[4], bl[4];
                LDSM4(bh, baddr);
                LDSM4(bl, baddr + BBYTES);
                MMA(acc[2*tt],   ah, bh[0], bh[1]);
                MMA(acc[2*tt],   ah, bl[0], bl[1]);
                MMA(acc[2*tt],   al, bh[0], bh[1]);
                MMA(acc[2*tt+1], ah, bh[2], bh[3]);
                MMA(acc[2*tt+1], ah, bl[2], bl[3]);
                MMA(acc[2*tt+1], al, bh[2], bh[3]);
            }
        }
        __syncthreads();
    }
}

// -------- big GEMM: C[M,N] = A @ B^T (+bias), BM=128, BN=64 --------
template<bool BIAS>
__global__ __launch_bounds__(256)
void mma_gemm(const __nv_bfloat16* __restrict__ Ah, const __nv_bfloat16* __restrict__ Al,
              const __nv_bfloat16* __restrict__ Bh, const __nv_bfloat16* __restrict__ Bl,
              const float* __restrict__ bias, float* __restrict__ C, int Ntot)
{
    extern __shared__ char smem[];
    uint32_t sb = smem_u32(smem);
    const int bn = blockIdx.x, bm = blockIdx.y;
    const int lane = threadIdx.x & 31, wid = threadIdx.x >> 5;
    float acc[8][4] = {};
    mma_loop<64>(sb, Ah + (size_t)bm*128*KDIM, Al + (size_t)bm*128*KDIM,
                 Bh + (size_t)bn*64*KDIM, Bl + (size_t)bn*64*KDIM, acc);
    int row0 = bm*128 + wid*16 + (lane >> 2);
    #pragma unroll
    for (int nt = 0; nt < 8; nt++) {
        int col = bn*64 + nt*8 + (lane & 3)*2;
        float2 v0 = { acc[nt][0], acc[nt][1] };
        float2 v1 = { acc[nt][2], acc[nt][3] };
        if (BIAS) {
            float b0 = bias[col], b1 = bias[col+1];
            v0.x += b0; v0.y += b1; v1.x += b0; v1.y += b1;
        }
        *(float2*)&C[(size_t)row0*Ntot + col] = v0;
        *(float2*)&C[(size_t)(row0+8)*Ntot + col] = v1;
    }
}

// -------- fused GRU step: gh tile [128 x 48] + gate epilogue (16 triples/CTA) --------
template<bool STORE_OP>
__global__ __launch_bounds__(256)
void gru_step(const __nv_bfloat16* __restrict__ Ah, const __nv_bfloat16* __restrict__ Al,
              const __nv_bfloat16* __restrict__ Bh, const __nv_bfloat16* __restrict__ Bl,
              const float* __restrict__ gx, const float* __restrict__ bhh,
              float* __restrict__ h, __nv_bfloat16* __restrict__ hh_out, __nv_bfloat16* __restrict__ hl_out,
              float* __restrict__ op, __nv_bfloat16* __restrict__ oph, __nv_bfloat16* __restrict__ opl, int t)
{
    extern __shared__ char smem[];
    uint32_t sb = smem_u32(smem);
    const int bn = blockIdx.x;
    const int tid = threadIdx.x, lane = tid & 31, wid = tid >> 5;
    float acc[6][4] = {};
    mma_loop<48>(sb, Ah, Al, Bh + (size_t)bn*48*KDIM, Bl + (size_t)bn*48*KDIM, acc);

    // stage gh tile in smem (pitch 49 floats), then fused gate math
    float* gs = (float*)smem;
    int r0 = wid*16 + (lane >> 2);
    #pragma unroll
    for (int nt = 0; nt < 6; nt++) {
        int ccol = nt*8 + (lane & 3)*2;
        gs[r0*49 + ccol]     = acc[nt][0];
        gs[r0*49 + ccol + 1] = acc[nt][1];
        gs[(r0+8)*49 + ccol]     = acc[nt][2];
        gs[(r0+8)*49 + ccol + 1] = acc[nt][3];
    }
    __syncthreads();

    #pragma unroll
    for (int i = tid; i < 2048; i += 256) {
        int b = i >> 4, q = i & 15;
        int j = bn*16 + q;
        float rp = gs[b*49 + 3*q]     + bhh[j];
        float zp = gs[b*49 + 3*q + 1] + bhh[H + j];
        float np = gs[b*49 + 3*q + 2] + bhh[2*H + j];
        const float* gxr = gx + ((size_t)b * T + t) * G3;
        float rr = 1.f / (1.f + expf(-(gxr[j] + rp)));
        float zz = 1.f / (1.f + expf(-(gxr[H + j] + zp)));
        float nn = tanhf(gxr[2*H + j] + rr * np);
        float hp = h[(size_t)b*H + j];
        float hv = (1.f - zz) * nn + zz * hp;
        h[(size_t)b*H + j] = hv;
        __nv_bfloat16 hi = __float2bfloat16(hv);
        __nv_bfloat16 lo = __float2bfloat16(hv - __bfloat162float(hi));
        hh_out[(size_t)b*H + j] = hi;
        hl_out[(size_t)b*H + j] = lo;
        if (STORE_OP) {
            size_t o = ((size_t)t*B + b)*H + j;
            op[o] = hv; oph[o] = hi; opl[o] = lo;
        }
    }
}

// -------- small fp32 GEMM (M=128) and tail kernels --------
template<bool ACCUM>
__global__ void gemm_smallM(const float* __restrict__ A, const float* __restrict__ Bm,
                            float* __restrict__ Cm, int N, int K)
{
    __shared__ float As[16][128];
    __shared__ float Bs[16][32];
    int tid = threadIdx.x, bn = blockIdx.x * 32;
    int trow = (tid >> 3) * 8, tcol = (tid & 7) * 4;
    float acc[8][4] = {};
    for (int k0 = 0; k0 < K; k0 += 16) {
        #pragma unroll
        for (int l = 0; l < 4; l++) {
            int idx = tid + l * 128;
            int row = idx >> 2, k4 = (idx & 3) * 4;
            float4 av = *(const float4*)&A[(size_t)row*K + k0 + k4];
            As[k4+0][row] = av.x; As[k4+1][row] = av.y; As[k4+2][row] = av.z; As[k4+3][row] = av.w;
        }
        { int kr = tid >> 3, n4 = (tid & 7) * 4;
          float4 bv = *(const float4*)&Bm[(size_t)(k0 + kr)*N + bn + n4];
          *(float4*)&Bs[kr][n4] = bv; }
        __syncthreads();
        #pragma unroll
        for (int k = 0; k < 16; k++) {
            float b0 = Bs[k][tcol], b1 = Bs[k][tcol+1], b2 = Bs[k][tcol+2], b3 = Bs[k][tcol+3];
            #pragma unroll
            for (int i = 0; i < 8; i++) {
                float a = As[k][trow + i];
                acc[i][0] += a*b0; acc[i][1] += a*b1; acc[i][2] += a*b2; acc[i][3] += a*b3;
            }
        }
        __syncthreads();
    }
    #pragma unroll
    for (int i = 0; i < 8; i++) {
        float4 v = { acc[i][0], acc[i][1], acc[i][2], acc[i][3] };
        float* Cr = &Cm[(size_t)(trow + i)*N + bn + tcol];
        if (ACCUM) { float4 o = *(float4*)Cr; v.x += o.x; v.y += o.y; v.z += o.z; v.w += o.w; }
        *(float4*)Cr = v;
    }
}
__global__ void scores_kernel(const float* __restrict__ wy, const float* __restrict__ wh,
                              const float* __restrict__ wa, float* __restrict__ sc)
{
    int warp = threadIdx.x >> 5, lane = threadIdx.x & 31;
    int p = blockIdx.x * 4 + warp;
    int t = p >> 7, b = p & 127;
    const float* wyr = wy + (size_t)p * H;
    const float* whr = wh + (size_t)b * H;
    float acc = 0.f;
    for (int hh = lane; hh < H; hh += 32) acc += tanhf(wyr[hh] + whr[hh]) * wa[hh];
    #pragma unroll
    for (int o = 16; o > 0; o >>= 1) acc += __shfl_xor_sync(0xffffffff, acc, o);
    if (lane == 0) sc[b*T + t] = acc;
}
__global__ void softmax_kernel(const float* __restrict__ sc, float* __restrict__ al)
{
    __shared__ float s[128];
    int b = blockIdx.x, t = threadIdx.x;
    float v = sc[b*T + t];
    s[t] = v; __syncthreads();
    for (int o = 64; o > 0; o >>= 1) { if (t < o) s[t] = fmaxf(s[t], s[t+o]); __syncthreads(); }
    float mx = s[0]; __syncthreads();
    float e = expf(v - mx);
    s[t] = e; __syncthreads();
    for (int o = 64; o > 0; o >>= 1) { if (t < o) s[t] += s[t+o]; __syncthreads(); }
    al[b*T + t] = e / s[0];
}
__global__ void rweight_kernel(const float* __restrict__ al, const float* __restrict__ op, float* __restrict__ r)
{
    int idx = blockIdx.x * blockDim.x + threadIdx.x;
    int b = idx >> 10, j = idx & 1023;
    float acc = 0.f;
    #pragma unroll 4
    for (int t = 0; t < T; t++) acc += al[b*T + t] * op[((size_t)t*B + b)*H + j];
    r[idx] = acc;
}
__global__ void out_kernel(const float* __restrict__ tmp, const float* __restrict__ ow,
                           const float* __restrict__ ob, float* __restrict__ out)
{
    __shared__ float s0[128], s1[128], s2[128];
    int b = blockIdx.x, tid = threadIdx.x;
    float p0 = 0.f, p1 = 0.f, p2 = 0.f;
    for (int hh = tid; hh < H; hh += 128) {
        float hs = tanhf(tmp[(size_t)b*H + hh]);
        p0 += hs * ow[hh]; p1 += hs * ow[H + hh]; p2 += hs * ow[2*H + hh];
    }
    s0[tid] = p0; s1[tid] = p1; s2[tid] = p2; __syncthreads();
    for (int o = 64; o > 0; o >>= 1) {
        if (tid < o) { s0[tid] += s0[tid+o]; s1[tid] += s1[tid+o]; s2[tid] += s2[tid+o]; }
        __syncthreads();
    }
    if (tid == 0) {
        float l0 = tanhf(s0[0] + ob[0]), l1 = tanhf(s1[0] + ob[1]), l2 = tanhf(s2[0] + ob[2]);
        float mx = fmaxf(l0, fmaxf(l1, l2));
        float lse = mx + logf(expf(l0-mx) + expf(l1-mx) + expf(l2-mx));
        out[b*3] = l0 - lse; out[b*3+1] = l1 - lse; out[b*3+2] = l2 - lse;
    }
}

// -------- launch --------
extern "C" void kernel_launch(void* const* d_in, const int* in_sizes, int n_in,
                              void* d_out, int out_size)
{
    const float* premise    = (const float*)d_in[0];
    const float* hypothesis = (const float*)d_in[1];
    const float* p_Wih = (const float*)d_in[2];
    const float* p_Whh = (const float*)d_in[3];
    const float* p_bih = (const float*)d_in[4];
    const float* p_bhh = (const float*)d_in[5];
    const float* h_Wih = (const float*)d_in[6];
    const float* h_Whh = (const float*)d_in[7];
    const float* h_bih = (const float*)d_in[8];
    const float* h_bhh = (const float*)d_in[9];
    const float* W_y = (const float*)d_in[10];
    const float* W_h = (const float*)d_in[11];
    const float* W_alpha = (const float*)d_in[12];
    const float* W_x = (const float*)d_in[13];
    const float* W_p = (const float*)d_in[14];
    const float* out_w = (const float*)d_in[15];
    const float* out_b = (const float*)d_in[16];
    float* out = (float*)d_out;

    float *gx, *op, *h, *wh, *sc, *al, *rr, *tmp;
    __nv_bfloat16 *oph, *opl, *xh, *xl, *wih_h, *wih_l, *wp_h, *wp_l, *wyt_h, *wyt_l, *hhA, *hlA, *hhB, *hlB;
    cudaGetSymbolAddress((void**)&gx, g_gx);   cudaGetSymbolAddress((void**)&op, g_op);
    cudaGetSymbolAddress((void**)&oph, g_oph); cudaGetSymbolAddress((void**)&opl, g_opl);
    cudaGetSymbolAddress((void**)&xh, g_xh);   cudaGetSymbolAddress((void**)&xl, g_xl);
    cudaGetSymbolAddress((void**)&wih_h, g_wih_h); cudaGetSymbolAddress((void**)&wih_l, g_wih_l);
    cudaGetSymbolAddress((void**)&wp_h, g_wp_h);   cudaGetSymbolAddress((void**)&wp_l, g_wp_l);
    cudaGetSymbolAddress((void**)&wyt_h, g_wyt_h); cudaGetSymbolAddress((void**)&wyt_l, g_wyt_l);
    cudaGetSymbolAddress((void**)&h, g_h);
    cudaGetSymbolAddress((void**)&hhA, g_hhA); cudaGetSymbolAddress((void**)&hlA, g_hlA);
    cudaGetSymbolAddress((void**)&hhB, g_hhB); cudaGetSymbolAddress((void**)&hlB, g_hlB);
    cudaGetSymbolAddress((void**)&wh, g_wh); cudaGetSymbolAddress((void**)&sc, g_sc);
    cudaGetSymbolAddress((void**)&al, g_al); cudaGetSymbolAddress((void**)&rr, g_r);
    cudaGetSymbolAddress((void**)&tmp, g_tmp);

    // smem: per-buffer = 2*A(18432) + 2*B(NT*144); double-buffered
    const int GSMEM = 2 * (2*ABYTES + 2*64*PITCH);   // 110592
    const int RSMEM = 2 * (2*ABYTES + 2*48*PITCH);   // 101376
    cudaFuncSetAttribute(mma_gemm<true>,  cudaFuncAttributeMaxDynamicSharedMemorySize, GSMEM);
    cudaFuncSetAttribute(mma_gemm<false>, cudaFuncAttributeMaxDynamicSharedMemorySize, GSMEM);
    cudaFuncSetAttribute(gru_step<true>,  cudaFuncAttributeMaxDynamicSharedMemorySize, RSMEM);
    cudaFuncSetAttribute(gru_step<false>, cudaFuncAttributeMaxDynamicSharedMemorySize, RSMEM);

    cudaMemsetAsync(h, 0, (size_t)B*H*sizeof(float));
    cudaMemsetAsync(hhA, 0, (size_t)B*H*sizeof(__nv_bfloat16));
    cudaMemsetAsync(hlA, 0, (size_t)B*H*sizeof(__nv_bfloat16));

    // ---- premise GRU ----
    split4<<<(B*T*H/4)/256, 256>>>((const float4*)premise, (__nv_bfloat162*)xh, (__nv_bfloat162*)xl);
    split4<<<(G3*H/4)/256, 256>>>((const float4*)p_Wih, (__nv_bfloat162*)wih_h, (__nv_bfloat162*)wih_l);
    perm_split<<<(G3*H/4)/256, 256>>>(p_Whh, wp_h, wp_l);
    mma_gemm<true><<<dim3(G3/64, (B*T)/128), 256, GSMEM>>>(xh, xl, wih_h, wih_l, p_bih, gx, G3);

    __nv_bfloat16 *chA = hhA, *clA = hlA, *chB = hhB, *clB = hlB;
    for (int t = 0; t < T; t++) {
        gru_step<true><<<64, 256, RSMEM>>>(chA, clA, wp_h, wp_l, gx, p_bhh, h, chB, clB, op, oph, opl, t);
        __nv_bfloat16* s;
        s = chA; chA = chB; chB = s;
        s = clA; clA = clB; clB = s;
    }

    // ---- hypothesis GRU (reuse buffers) ----
    split4<<<(B*T*H/4)/256, 256>>>((const float4*)hypothesis, (__nv_bfloat162*)xh, (__nv_bfloat162*)xl);
    split4<<<(G3*H/4)/256, 256>>>((const float4*)h_Wih, (__nv_bfloat162*)wih_h, (__nv_bfloat162*)wih_l);
    perm_split<<<(G3*H/4)/256, 256>>>(h_Whh, wp_h, wp_l);
    mma_gemm<true><<<dim3(G3/64, (B*T)/128), 256, GSMEM>>>(xh, xl, wih_h, wih_l, h_bih, gx, G3);
    for (int t = 0; t < T; t++) {
        gru_step<false><<<64, 256, RSMEM>>>(chA, clA, wp_h, wp_l, gx, h_bhh, h, chB, clB, nullptr, nullptr, nullptr, t);
        __nv_bfloat16* s;
        s = chA; chA = chB; chB = s;
        s = clA; clA = clB; clB = s;
    }
    // h == o_h[-1] (fp32)

    // ---- attention + classifier ----
    trans_split<<<(H*H)/256, 256>>>(W_y, wyt_h, wyt_l);
    float* wy = gx;  // reuse
    mma_gemm<false><<<dim3(H/64, (T*B)/128), 256, GSMEM>>>(oph, opl, wyt_h, wyt_l, nullptr, wy, H);
    gemm_smallM<false><<<H/32, 128>>>(h, W_h, wh, H, H);
    scores_kernel<<<(T*B)/4, 128>>>(wy, wh, W_alpha, sc);
    softmax_kernel<<<B, 128>>>(sc, al);
    rweight_kernel<<<(B*H)/256, 256>>>(al, op, rr);
    gemm_smallM<false><<<H/32, 128>>>(rr, W_p, tmp, H, H);
    gemm_smallM<true><<<H/32, 128>>>(h, W_x, tmp, H, H);
    out_kernel<<<B, 128>>>(tmp, out_w, out_b, out);
}

// round 16
// speedup vs baseline: 2.7817x; 1.1380x over previous
#include <cuda_runtime.h>
#include <cuda_bf16.h>
#include <math.h>
#include <stdint.h>

#define H 1024
#define B 128
#define T 128
#define G3 3072
#define KDIM 1024
#define NCHUNK 16

__device__ __forceinline__ uint32_t smem_u32(const void* p) {
    uint32_t a;
    asm("{ .reg .u64 t; cvta.to.shared.u64 t, %1; cvt.u32.u64 %0, t; }" : "=r"(a) : "l"(p));
    return a;
}
__device__ __forceinline__ void cp16(uint32_t s, const void* g) {
    asm volatile("cp.async.cg.shared.global [%0], [%1], 16;" :: "r"(s), "l"(g));
}
#define CP_COMMIT() asm volatile("cp.async.commit_group;" ::: "memory")
#define CP_WAIT(n) asm volatile("cp.async.wait_group %0;" :: "n"(n) : "memory")
#define LDSM4(r, addr) asm volatile("ldmatrix.sync.aligned.m8n8.x4.shared.b16 {%0,%1,%2,%3}, [%4];" \
    : "=r"((r)[0]),"=r"((r)[1]),"=r"((r)[2]),"=r"((r)[3]) : "r"(addr))
#define MMA(cc, a, b0, b1) asm volatile( \
    "mma.sync.aligned.m16n8k16.row.col.f32.bf16.bf16.f32 {%0,%1,%2,%3},{%4,%5,%6,%7},{%8,%9},{%0,%1,%2,%3};" \
    : "+f"((cc)[0]),"+f"((cc)[1]),"+f"((cc)[2]),"+f"((cc)[3]) \
    : "r"((a)[0]),"r"((a)[1]),"r"((a)[2]),"r"((a)[3]), "r"(b0),"r"(b1))

#define PITCH 144
#define ABYTES (128*PITCH)   // 18432

#define DEVG __device__ __align__(256)
DEVG float g_gx[(size_t)B*T*G3];     // premise gates_x; later reused as Wy
DEVG float g_gx2[(size_t)B*T*G3];    // hypothesis gates_x
DEVG float g_op[(size_t)B*T*H];
DEVG __nv_bfloat16 g_oph[(size_t)B*T*H];
DEVG __nv_bfloat16 g_opl[(size_t)B*T*H];
DEVG __nv_bfloat16 g_xh[(size_t)B*T*H];
DEVG __nv_bfloat16 g_xl[(size_t)B*T*H];
DEVG __nv_bfloat16 g_wih_h[(size_t)G3*H];
DEVG __nv_bfloat16 g_wih_l[(size_t)G3*H];
DEVG __nv_bfloat16 g_wp_h[(size_t)G3*H];   // premise Whh split
DEVG __nv_bfloat16 g_wp_l[(size_t)G3*H];
DEVG __nv_bfloat16 g_wq_h[(size_t)G3*H];   // hypothesis Whh split
DEVG __nv_bfloat16 g_wq_l[(size_t)G3*H];
DEVG __nv_bfloat16 g_wyt_h[(size_t)H*H];
DEVG __nv_bfloat16 g_wyt_l[(size_t)H*H];
DEVG float g_h[B*H];
DEVG __nv_bfloat16 g_hh[B*H], g_hl[B*H];
DEVG float g_gh[B*G3];
DEVG float g_wh[B*H];
DEVG float g_sc[B*T];
DEVG float g_al[B*T];
DEVG float g_r[B*H];
DEVG float g_tmp[B*H];
__device__ unsigned g_bar;

// -------- prep: fp32 -> bf16 hi/lo split --------
__global__ void split4(const float4* __restrict__ x, __nv_bfloat162* __restrict__ hi, __nv_bfloat162* __restrict__ lo)
{
    size_t i = (size_t)blockIdx.x * blockDim.x + threadIdx.x;
    float4 v = x[i];
    __nv_bfloat16 h0 = __float2bfloat16(v.x), h1 = __float2bfloat16(v.y);
    __nv_bfloat16 h2 = __float2bfloat16(v.z), h3 = __float2bfloat16(v.w);
    __nv_bfloat162 a, b;
    a.x = h0; a.y = h1; b.x = h2; b.y = h3;
    hi[2*i] = a; hi[2*i+1] = b;
    a.x = __float2bfloat16(v.x - __bfloat162float(h0));
    a.y = __float2bfloat16(v.y - __bfloat162float(h1));
    b.x = __float2bfloat16(v.z - __bfloat162float(h2));
    b.y = __float2bfloat16(v.w - __bfloat162float(h3));
    lo[2*i] = a; lo[2*i+1] = b;
}
__global__ void trans_split(const float* __restrict__ Wy, __nv_bfloat16* __restrict__ th, __nv_bfloat16* __restrict__ tl)
{
    int i = blockIdx.x * blockDim.x + threadIdx.x;
    int n = i >> 10, k = i & 1023;
    float v = Wy[(size_t)k*H + n];
    __nv_bfloat16 hh = __float2bfloat16(v);
    th[(size_t)n*H + k] = hh;
    tl[(size_t)n*H + k] = __float2bfloat16(v - __bfloat162float(hh));
}

// -------- shared bf16x3 K-loop (big GEMM): 8 warps, each 16 rows x 64 cols --------
__device__ __forceinline__ void mma_loop64(uint32_t sb,
    const __nv_bfloat16* __restrict__ Ah, const __nv_bfloat16* __restrict__ Al,
    const __nv_bfloat16* __restrict__ Bh, const __nv_bfloat16* __restrict__ Bl,
    float acc[][4])
{
    const int tid = threadIdx.x, lane = tid & 31, wid = tid >> 5;
    const uint32_t BOFF = 2 * ABYTES;
    const uint32_t BBYTES = 64 * PITCH;
    const uint32_t BUFB = BOFF + 2 * BBYTES;
    const int lr = lane & 7;
    const uint32_t arow = (uint32_t)(wid*16 + lr + ((lane >> 3) & 1) * 8);
    const uint32_t acol8 = (uint32_t)((lane >> 4) * 8);
    const uint32_t brow_off = (uint32_t)(lr + (lane >> 4) * 8);
    const uint32_t bcol8 = (uint32_t)(((lane >> 3) & 1) * 8);

    auto load_chunk = [&](int c) {
        uint32_t s0 = sb + (uint32_t)(c & 1) * BUFB;
        int k0 = c * 64;
        #pragma unroll
        for (int i = tid; i < 2048; i += 256) {
            int hl = i >> 10, r = (i >> 3) & 127, s = i & 7;
            cp16(s0 + (uint32_t)(hl*ABYTES + r*PITCH + s*16),
                 (hl ? Al : Ah) + (size_t)r*KDIM + k0 + s*8);
        }
        #pragma unroll
        for (int i = tid; i < 1024; i += 256) {
            int hl = i >> 9;
            int r = (i >> 3) & 63, s = i & 7;
            cp16(s0 + BOFF + (uint32_t)hl*BBYTES + (uint32_t)(r*PITCH + s*16),
                 (hl ? Bl : Bh) + (size_t)r*KDIM + k0 + s*8);
        }
        CP_COMMIT();
    };
    load_chunk(0);
    for (int c = 0; c < NCHUNK; c++) {
        if (c < NCHUNK - 1) { load_chunk(c + 1); CP_WAIT(1); }
        else CP_WAIT(0);
        __syncthreads();
        uint32_t s0 = sb + (uint32_t)(c & 1) * BUFB;
        #pragma unroll
        for (int ks = 0; ks < 4; ks++) {
            uint32_t aaddr = s0 + arow*PITCH + (ks*16 + acol8)*2;
            uint32_t ah[4], al[4];
            LDSM4(ah, aaddr);
            LDSM4(al, aaddr + ABYTES);
            #pragma unroll
            for (int tt = 0; tt < 4; tt++) {
                uint32_t baddr = s0 + BOFF + (tt*16 + brow_off)*PITCH + (ks*16 + bcol8)*2;
                uint32_t bh[4], bl[4];
                LDSM4(bh, baddr);
                LDSM4(bl, baddr + BBYTES);
                MMA(acc[2*tt],   ah, bh[0], bh[1]);
                MMA(acc[2*tt],   ah, bl[0], bl[1]);
                MMA(acc[2*tt],   al, bh[0], bh[1]);
                MMA(acc[2*tt+1], ah, bh[2], bh[3]);
                MMA(acc[2*tt+1], ah, bl[2], bl[3]);
                MMA(acc[2*tt+1], al, bh[2], bh[3]);
            }
        }
        __syncthreads();
    }
}

template<bool BIAS>
__global__ __launch_bounds__(256)
void mma_gemm(const __nv_bfloat16* __restrict__ Ah, const __nv_bfloat16* __restrict__ Al,
              const __nv_bfloat16* __restrict__ Bh, const __nv_bfloat16* __restrict__ Bl,
              const float* __restrict__ bias, float* __restrict__ C, int Ntot)
{
    extern __shared__ char smem[];
    uint32_t sb = smem_u32(smem);
    const int bn = blockIdx.x, bm = blockIdx.y;
    const int lane = threadIdx.x & 31, wid = threadIdx.x >> 5;
    float acc[8][4] = {};
    mma_loop64(sb, Ah + (size_t)bm*128*KDIM, Al + (size_t)bm*128*KDIM,
               Bh + (size_t)bn*64*KDIM, Bl + (size_t)bn*64*KDIM, acc);
    int row0 = bm*128 + wid*16 + (lane >> 2);
    #pragma unroll
    for (int nt = 0; nt < 8; nt++) {
        int col = bn*64 + nt*8 + (lane & 3)*2;
        float2 v0 = { acc[nt][0], acc[nt][1] };
        float2 v1 = { acc[nt][2], acc[nt][3] };
        if (BIAS) {
            float b0 = bias[col], b1 = bias[col+1];
            v0.x += b0; v0.y += b1; v1.x += b0; v1.y += b1;
        }
        *(float2*)&C[(size_t)row0*Ntot + col] = v0;
        *(float2*)&C[(size_t)(row0+8)*Ntot + col] = v1;
    }
}

// -------- persistent recurrence: 96 CTAs, grid barrier, weights in smem --------
__device__ __forceinline__ void grid_bar(unsigned target) {
    __syncthreads();
    if (threadIdx.x == 0) {
        __threadfence();
        atomicAdd(&g_bar, 1u);
        while (atomicAdd(&g_bar, 0u) < target) { }
        __threadfence();
    }
    __syncthreads();
}

__global__ __launch_bounds__(256)
void gru_persist(const __nv_bfloat16* __restrict__ wpA_h, const __nv_bfloat16* __restrict__ wpA_l,
                 const __nv_bfloat16* __restrict__ wpB_h, const __nv_bfloat16* __restrict__ wpB_l,
                 const float* __restrict__ gx_p, const float* __restrict__ gx_h,
                 const float* __restrict__ bhh_p, const float* __restrict__ bhh_h,
                 float* __restrict__ h, __nv_bfloat16* __restrict__ hh, __nv_bfloat16* __restrict__ hl,
                 float* __restrict__ gh,
                 float* __restrict__ op, __nv_bfloat16* __restrict__ oph, __nv_bfloat16* __restrict__ opl)
{
    extern __shared__ char smem[];
    uint32_t sb = smem_u32(smem);
    const int tid = threadIdx.x, lane = tid & 31, wid = tid >> 5;
    const int bn = blockIdx.x;                 // 0..95, owns cols [bn*32, bn*32+32)
    const uint32_t B0 = sb + 73728u;           // weights: hi [B0,B0+73728), lo [B0+73728,B0+147456)
    const int lr = lane & 7;
    const uint32_t arow = (uint32_t)(wid*16 + lr + ((lane >> 3) & 1) * 8);
    const uint32_t acol8 = (uint32_t)((lane >> 4) * 8);
    const uint32_t brow_off = (uint32_t)(lr + (lane >> 4) * 8);
    const uint32_t bcol8 = (uint32_t)(((lane >> 3) & 1) * 8);
    unsigned tgt = 0;

    auto load_weights = [&](const __nv_bfloat16* Wh_, const __nv_bfloat16* Wl_) {
        for (int i = tid; i < 4096; i += 256) {
            int c = i >> 8, r = (i >> 3) & 31, s = i & 7;
            uint32_t off = (uint32_t)(c*4608 + r*PITCH + s*16);
            size_t go = (size_t)(bn*32 + r)*KDIM + c*64 + s*8;
            cp16(B0 + off, Wh_ + go);
            cp16(B0 + 73728u + off, Wl_ + go);
        }
        CP_COMMIT(); CP_WAIT(0); __syncthreads();
    };

    load_weights(wpA_h, wpA_l);

    for (int t = 0; t < 2*T; t++) {
        if (t == T) load_weights(wpB_h, wpB_l);
        const float* gx = (t < T) ? gx_p : gx_h;
        const float* bhh = (t < T) ? bhh_p : bhh_h;
        const int ts = (t < T) ? t : t - T;

        // ---- phase A: gh slice = h @ Whh^T (bf16x3) ----
        float acc[4][4] = {};
        auto loadA = [&](int c) {
            uint32_t s0 = sb + (uint32_t)(c & 1) * 36864u;
            int k0 = c * 64;
            #pragma unroll
            for (int i = tid; i < 2048; i += 256) {
                int half = i >> 10, r = (i >> 3) & 127, s = i & 7;
                cp16(s0 + (uint32_t)(half*18432 + r*PITCH + s*16),
                     (half ? hl : hh) + (size_t)r*KDIM + k0 + s*8);
            }
            CP_COMMIT();
        };
        loadA(0);
        for (int c = 0; c < NCHUNK; c++) {
            if (c < NCHUNK - 1) { loadA(c + 1); CP_WAIT(1); }
            else CP_WAIT(0);
            __syncthreads();
            uint32_t s0 = sb + (uint32_t)(c & 1) * 36864u;
            uint32_t bc = B0 + (uint32_t)c * 4608u;
            #pragma unroll
            for (int ks = 0; ks < 4; ks++) {
                uint32_t aaddr = s0 + arow*PITCH + (ks*16 + acol8)*2;
                uint32_t ah[4], al[4];
                LDSM4(ah, aaddr);
                LDSM4(al, aaddr + 18432);
                #pragma unroll
                for (int q = 0; q < 2; q++) {
                    uint32_t baddr = bc + (q*16 + brow_off)*PITCH + (ks*16 + bcol8)*2;
                    uint32_t bh_[4], bl_[4];
                    LDSM4(bh_, baddr);
                    LDSM4(bl_, baddr + 73728u);
                    MMA(acc[2*q],   ah, bh_[0], bh_[1]);
                    MMA(acc[2*q],   ah, bl_[0], bl_[1]);
                    MMA(acc[2*q],   al, bh_[0], bh_[1]);
                    MMA(acc[2*q+1], ah, bh_[2], bh_[3]);
                    MMA(acc[2*q+1], ah, bl_[2], bl_[3]);
                    MMA(acc[2*q+1], al, bh_[2], bh_[3]);
                }
            }
            __syncthreads();
        }
        {
            int row0 = wid*16 + (lane >> 2);
            #pragma unroll
            for (int q = 0; q < 4; q++) {
                int col = bn*32 + q*8 + (lane & 3)*2;
                *(float2*)&gh[(size_t)row0*G3 + col]     = make_float2(acc[q][0], acc[q][1]);
                *(float2*)&gh[(size_t)(row0+8)*G3 + col] = make_float2(acc[q][2], acc[q][3]);
            }
        }
        tgt += 96; grid_bar(tgt);

        // ---- phase B: elementwise gates over all CTAs ----
        for (int i = bn*256 + tid; i < B*H; i += 96*256) {
            int b = i >> 10, j = i & 1023;
            const float* gxr = gx + ((size_t)b*T + ts)*G3;
            const float* ghr = gh + (size_t)b*G3;
            float rp = ghr[j]       + bhh[j];
            float zp = ghr[H + j]   + bhh[H + j];
            float np = ghr[2*H + j] + bhh[2*H + j];
            float rr_ = 1.f / (1.f + expf(-(gxr[j] + rp)));
            float zz  = 1.f / (1.f + expf(-(gxr[H + j] + zp)));
            float nn  = tanhf(gxr[2*H + j] + rr_ * np);
            float hv = (1.f - zz) * nn + zz * h[i];
            h[i] = hv;
            __nv_bfloat16 hi_ = __float2bfloat16(hv);
            __nv_bfloat16 lo_ = __float2bfloat16(hv - __bfloat162float(hi_));
            hh[i] = hi_;
            hl[i] = lo_;
            if (t < T) {
                size_t o = ((size_t)ts*B + b)*H + j;
                op[o] = hv; oph[o] = hi_; opl[o] = lo_;
            }
        }
        tgt += 96; grid_bar(tgt);
    }
}

// -------- small fp32 GEMM (M=128) and tail kernels --------
template<bool ACCUM>
__global__ void gemm_smallM(const float* __restrict__ A, const float* __restrict__ Bm,
                            float* __restrict__ Cm, int N, int K)
{
    __shared__ float As[16][128];
    __shared__ float Bs[16][32];
    int tid = threadIdx.x, bn = blockIdx.x * 32;
    int trow = (tid >> 3) * 8, tcol = (tid & 7) * 4;
    float acc[8][4] = {};
    for (int k0 = 0; k0 < K; k0 += 16) {
        #pragma unroll
        for (int l = 0; l < 4; l++) {
            int idx = tid + l * 128;
            int row = idx >> 2, k4 = (idx & 3) * 4;
            float4 av = *(const float4*)&A[(size_t)row*K + k0 + k4];
            As[k4+0][row] = av.x; As[k4+1][row] = av.y; As[k4+2][row] = av.z; As[k4+3][row] = av.w;
        }
        { int kr = tid >> 3, n4 = (tid & 7) * 4;
          float4 bv = *(const float4*)&Bm[(size_t)(k0 + kr)*N + bn + n4];
          *(float4*)&Bs[kr][n4] = bv; }
        __syncthreads();
        #pragma unroll
        for (int k = 0; k < 16; k++) {
            float b0 = Bs[k][tcol], b1 = Bs[k][tcol+1], b2 = Bs[k][tcol+2], b3 = Bs[k][tcol+3];
            #pragma unroll
            for (int i = 0; i < 8; i++) {
                float a = As[k][trow + i];
                acc[i][0] += a*b0; acc[i][1] += a*b1; acc[i][2] += a*b2; acc[i][3] += a*b3;
            }
        }
        __syncthreads();
    }
    #pragma unroll
    for (int i = 0; i < 8; i++) {
        float4 v = { acc[i][0], acc[i][1], acc[i][2], acc[i][3] };
        float* Cr = &Cm[(size_t)(trow + i)*N + bn + tcol];
        if (ACCUM) { float4 o = *(float4*)Cr; v.x += o.x; v.y += o.y; v.z += o.z; v.w += o.w; }
        *(float4*)Cr = v;
    }
}
__global__ void scores_kernel(const float* __restrict__ wy, const float* __restrict__ wh,
                              const float* __restrict__ wa, float* __restrict__ sc)
{
    int warp = threadIdx.x >> 5, lane = threadIdx.x & 31;
    int p = blockIdx.x * 4 + warp;
    int t = p >> 7, b = p & 127;
    const float* wyr = wy + (size_t)p * H;
    const float* whr = wh + (size_t)b * H;
    float acc = 0.f;
    for (int hh = lane; hh < H; hh += 32) acc += tanhf(wyr[hh] + whr[hh]) * wa[hh];
    #pragma unroll
    for (int o = 16; o > 0; o >>= 1) acc += __shfl_xor_sync(0xffffffff, acc, o);
    if (lane == 0) sc[b*T + t] = acc;
}
__global__ void softmax_kernel(const float* __restrict__ sc, float* __restrict__ al)
{
    __shared__ float s[128];
    int b = blockIdx.x, t = threadIdx.x;
    float v = sc[b*T + t];
    s[t] = v; __syncthreads();
    for (int o = 64; o > 0; o >>= 1) { if (t < o) s[t] = fmaxf(s[t], s[t+o]); __syncthreads(); }
    float mx = s[0]; __syncthreads();
    float e = expf(v - mx);
    s[t] = e; __syncthreads();
    for (int o = 64; o > 0; o >>= 1) { if (t < o) s[t] += s[t+o]; __syncthreads(); }
    al[b*T + t] = e / s[0];
}
__global__ void rweight_kernel(const float* __restrict__ al, const float* __restrict__ op, float* __restrict__ r)
{
    int idx = blockIdx.x * blockDim.x + threadIdx.x;
    int b = idx >> 10, j = idx & 1023;
    float acc = 0.f;
    #pragma unroll 4
    for (int t = 0; t < T; t++) acc += al[b*T + t] * op[((size_t)t*B + b)*H + j];
    r[idx] = acc;
}
__global__ void out_kernel(const float* __restrict__ tmp, const float* __restrict__ ow,
                           const float* __restrict__ ob, float* __restrict__ out)
{
    __shared__ float s0[128], s1[128], s2[128];
    int b = blockIdx.x, tid = threadIdx.x;
    float p0 = 0.f, p1 = 0.f, p2 = 0.f;
    for (int hh = tid; hh < H; hh += 128) {
        float hs = tanhf(tmp[(size_t)b*H + hh]);
        p0 += hs * ow[hh]; p1 += hs * ow[H + hh]; p2 += hs * ow[2*H + hh];
    }
    s0[tid] = p0; s1[tid] = p1; s2[tid] = p2; __syncthreads();
    for (int o = 64; o > 0; o >>= 1) {
        if (tid < o) { s0[tid] += s0[tid+o]; s1[tid] += s1[tid+o]; s2[tid] += s2[tid+o]; }
        __syncthreads();
    }
    if (tid == 0) {
        float l0 = tanhf(s0[0] + ob[0]), l1 = tanhf(s1[0] + ob[1]), l2 = tanhf(s2[0] + ob[2]);
        float mx = fmaxf(l0, fmaxf(l1, l2));
        float lse = mx + logf(expf(l0-mx) + expf(l1-mx) + expf(l2-mx));
        out[b*3] = l0 - lse; out[b*3+1] = l1 - lse; out[b*3+2] = l2 - lse;
    }
}

// -------- launch --------
extern "C" void kernel_launch(void* const* d_in, const int* in_sizes, int n_in,
                              void* d_out, int out_size)
{
    const float* premise    = (const float*)d_in[0];
    const float* hypothesis = (const float*)d_in[1];
    const float* p_Wih = (const float*)d_in[2];
    const float* p_Whh = (const float*)d_in[3];
    const float* p_bih = (const float*)d_in[4];
    const float* p_bhh = (const float*)d_in[5];
    const float* h_Wih = (const float*)d_in[6];
    const float* h_Whh = (const float*)d_in[7];
    const float* h_bih = (const float*)d_in[8];
    const float* h_bhh = (const float*)d_in[9];
    const float* W_y = (const float*)d_in[10];
    const float* W_h = (const float*)d_in[11];
    const float* W_alpha = (const float*)d_in[12];
    const float* W_x = (const float*)d_in[13];
    const float* W_p = (const float*)d_in[14];
    const float* out_w = (const float*)d_in[15];
    const float* out_b = (const float*)d_in[16];
    float* out = (float*)d_out;

    float *gx, *gx2, *op, *h, *gh, *wh, *sc, *al, *rr, *tmp;
    __nv_bfloat16 *oph, *opl, *xh, *xl, *wih_h, *wih_l, *wp_h, *wp_l, *wq_h, *wq_l, *wyt_h, *wyt_l, *hh, *hl;
    unsigned* barp;
    cudaGetSymbolAddress((void**)&gx, g_gx);   cudaGetSymbolAddress((void**)&gx2, g_gx2);
    cudaGetSymbolAddress((void**)&op, g_op);
    cudaGetSymbolAddress((void**)&oph, g_oph); cudaGetSymbolAddress((void**)&opl, g_opl);
    cudaGetSymbolAddress((void**)&xh, g_xh);   cudaGetSymbolAddress((void**)&xl, g_xl);
    cudaGetSymbolAddress((void**)&wih_h, g_wih_h); cudaGetSymbolAddress((void**)&wih_l, g_wih_l);
    cudaGetSymbolAddress((void**)&wp_h, g_wp_h);   cudaGetSymbolAddress((void**)&wp_l, g_wp_l);
    cudaGetSymbolAddress((void**)&wq_h, g_wq_h);   cudaGetSymbolAddress((void**)&wq_l, g_wq_l);
    cudaGetSymbolAddress((void**)&wyt_h, g_wyt_h); cudaGetSymbolAddress((void**)&wyt_l, g_wyt_l);
    cudaGetSymbolAddress((void**)&h, g_h);
    cudaGetSymbolAddress((void**)&hh, g_hh); cudaGetSymbolAddress((void**)&hl, g_hl);
    cudaGetSymbolAddress((void**)&gh, g_gh);
    cudaGetSymbolAddress((void**)&wh, g_wh); cudaGetSymbolAddress((void**)&sc, g_sc);
    cudaGetSymbolAddress((void**)&al, g_al); cudaGetSymbolAddress((void**)&rr, g_r);
    cudaGetSymbolAddress((void**)&tmp, g_tmp);
    cudaGetSymbolAddress((void**)&barp, g_bar);

    const int GSMEM = 2 * (2*ABYTES + 2*64*PITCH);   // 110592
    const int PSMEM = 4*ABYTES + 2*(16*32*PITCH);    // A dbl-buf 73728 + weights hi/lo 147456 = 221184
    cudaFuncSetAttribute(mma_gemm<true>,  cudaFuncAttributeMaxDynamicSharedMemorySize, GSMEM);
    cudaFuncSetAttribute(mma_gemm<false>, cudaFuncAttributeMaxDynamicSharedMemorySize, GSMEM);
    cudaFuncSetAttribute(gru_persist,     cudaFuncAttributeMaxDynamicSharedMemorySize, PSMEM);

    cudaMemsetAsync(barp, 0, sizeof(unsigned));
    cudaMemsetAsync(h, 0, (size_t)B*H*sizeof(float));
    cudaMemsetAsync(hh, 0, (size_t)B*H*sizeof(__nv_bfloat16));
    cudaMemsetAsync(hl, 0, (size_t)B*H*sizeof(__nv_bfloat16));

    // gates_x premise
    split4<<<(B*T*H/4)/256, 256>>>((const float4*)premise, (__nv_bfloat162*)xh, (__nv_bfloat162*)xl);
    split4<<<(G3*H/4)/256, 256>>>((const float4*)p_Wih, (__nv_bfloat162*)wih_h, (__nv_bfloat162*)wih_l);
    mma_gemm<true><<<dim3(G3/64, (B*T)/128), 256, GSMEM>>>(xh, xl, wih_h, wih_l, p_bih, gx, G3);
    // gates_x hypothesis
    split4<<<(B*T*H/4)/256, 256>>>((const float4*)hypothesis, (__nv_bfloat162*)xh, (__nv_bfloat162*)xl);
    split4<<<(G3*H/4)/256, 256>>>((const float4*)h_Wih, (__nv_bfloat162*)wih_h, (__nv_bfloat162*)wih_l);
    mma_gemm<true><<<dim3(G3/64, (B*T)/128), 256, GSMEM>>>(xh, xl, wih_h, wih_l, h_bih, gx2, G3);
    // Whh splits
    split4<<<(G3*H/4)/256, 256>>>((const float4*)p_Whh, (__nv_bfloat162*)wp_h, (__nv_bfloat162*)wp_l);
    split4<<<(G3*H/4)/256, 256>>>((const float4*)h_Whh, (__nv_bfloat162*)wq_h, (__nv_bfloat162*)wq_l);

    // persistent recurrence: both GRUs, 256 steps, one launch
    gru_persist<<<96, 256, PSMEM>>>(wp_h, wp_l, wq_h, wq_l, gx, gx2, p_bhh, h_bhh,
                                    h, hh, hl, gh, op, oph, opl);

    // attention + classifier
    trans_split<<<(H*H)/256, 256>>>(W_y, wyt_h, wyt_l);
    float* wy = gx;  // reuse premise gx
    mma_gemm<false><<<dim3(H/64, (T*B)/128), 256, GSMEM>>>(oph, opl, wyt_h, wyt_l, nullptr, wy, H);
    gemm_smallM<false><<<H/32, 128>>>(h, W_h, wh, H, H);
    scores_kernel<<<(T*B)/4, 128>>>(wy, wh, W_alpha, sc);
    softmax_kernel<<<B, 128>>>(sc, al);
    rweight_kernel<<<(B*H)/256, 256>>>(al, op, rr);
    gemm_smallM<false><<<H/32, 128>>>(rr, W_p, tmp, H, H);
    gemm_smallM<true><<<H/32, 128>>>(h, W_x, tmp, H, H);
    out_kernel<<<B, 128>>>(tmp, out_w, out_b, out);
}